// round 15
// baseline (speedup 1.0000x reference)
#include <cuda_runtime.h>
#include <cuda_fp16.h>
#include <math.h>
#include <stdint.h>

#define NROW   8
#define DCOLS  2097152
#define DD1    2048
#define DD2    1024
#define NBATCH 512
#define XELEMS (NBATCH * NROW * DD1)   // 8388608

// ---------------- scratch (static device globals; no allocations) ----------
__device__ unsigned char g_code[NROW * DCOLS];   // 16 MB: lattice codes (k0,k1) for vsum1
__device__ __half        g_wh[NROW * DCOLS];     // 16 MB  W fp16, natural [e][k][n]
__device__ __half        g_xh[XELEMS];           // 16 MB  x fp16
__device__ unsigned      g_minkey, g_maxkey;
__device__ float         g_s[3];                 // s0, s1, s2
__device__ float         g_sinv[3];              // 1/s0, 1/s1, 1/s2
__device__ float         g_thr[1024];            // sigm(thres_mean)
__device__ float         g_dmax[2];
__device__ int           g_counts[2][128];
__device__ int           g_rank_lut[128];
__device__ float         g_msp_tab[7 * 128];
__device__ unsigned char g_rs_tab[128];

// ---------------- helpers ---------------------------------------------------
__device__ __forceinline__ unsigned fencode(float f) {
    unsigned u = __float_as_uint(f);
    unsigned m = (unsigned)((int)u >> 31);
    return u ^ (m | 0x80000000u);
}
__device__ __forceinline__ float fdecode(unsigned k) {
    unsigned u = (k & 0x80000000u) ? (k ^ 0x80000000u) : ~k;
    return __uint_as_float(u);
}
__device__ __forceinline__ float sigm(float x) {
    return __fdiv_rn(1.0f, 1.0f + expf(-x));
}
__device__ __forceinline__ float decode_nv(unsigned char b, float s0, float s1) {
    float k0 = (float)((int)(b & 15u) - 8);
    float k1 = (float)((int)(b >> 4) - 2);
    return s0 * k0 + s1 * k1;
}

// value-only sort: fmin/fmax CE network directly on floats
__device__ __forceinline__ void sortf8(float a[8]) {
#define CEF(i, j) { float _lo = fminf(a[i], a[j]); float _hi = fmaxf(a[i], a[j]); a[i] = _lo; a[j] = _hi; }
    CEF(0,1) CEF(2,3) CEF(4,5) CEF(6,7)
    CEF(0,2) CEF(1,3) CEF(4,6) CEF(5,7)
    CEF(1,2) CEF(5,6) CEF(0,4) CEF(3,7)
    CEF(1,5) CEF(2,6)
    CEF(1,4) CEF(3,6)
    CEF(2,4) CEF(3,5)
    CEF(3,4)
#undef CEF
}
// packed u32 sort (index in low 3 bits)
__device__ __forceinline__ void sortu8(unsigned a[8]) {
#define CEU(i, j) { unsigned _lo = min(a[i], a[j]); unsigned _hi = max(a[i], a[j]); a[i] = _lo; a[j] = _hi; }
    CEU(0,1) CEU(2,3) CEU(4,5) CEU(6,7)
    CEU(0,2) CEU(1,3) CEU(4,6) CEU(5,7)
    CEU(1,2) CEU(5,6) CEU(0,4) CEU(3,7)
    CEU(1,5) CEU(2,6)
    CEU(1,4) CEU(3,6)
    CEU(2,4) CEU(3,5)
    CEU(3,4)
#undef CEU
}

__device__ __forceinline__ int column_code_fast(const float sv[8], float thr_dmax) {
    int code = 0;
#pragma unroll
    for (int i = 0; i < 7; i++)
        code = (code << 1) | ((sv[i + 1] - sv[i]) > thr_dmax ? 1 : 0);
    return code;
}
__device__ __forceinline__ float delta_max7(const float sv[8]) {
    float m = 0.0f;
#pragma unroll
    for (int i = 0; i < 7; i++) m = fmaxf(m, sv[i + 1] - sv[i]);
    return m;
}

// ---------------- PTX helpers -------------------------------------------------
__device__ __forceinline__ uint32_t smem_u32(const void* p) {
    uint32_t a;
    asm("{ .reg .u64 t; cvta.to.shared.u64 t, %1; cvt.u32.u64 %0, t; }" : "=r"(a) : "l"(p));
    return a;
}
#define CP_ASYNC16(dst, src) \
    asm volatile("cp.async.cg.shared.global [%0], [%1], 16;" :: "r"(dst), "l"(src))
#define CP_COMMIT() asm volatile("cp.async.commit_group;" ::: "memory")
#define CP_WAIT(n)  asm volatile("cp.async.wait_group %0;" :: "n"(n) : "memory")
#define SWZ128(b)   ((b) ^ (((b) >> 3) & 0x70))

__device__ __forceinline__ void ldsm_x4(uint32_t& r0, uint32_t& r1, uint32_t& r2,
                                        uint32_t& r3, uint32_t addr) {
    asm volatile("ldmatrix.sync.aligned.m8n8.x4.shared.b16 {%0,%1,%2,%3}, [%4];"
                 : "=r"(r0), "=r"(r1), "=r"(r2), "=r"(r3) : "r"(addr));
}
__device__ __forceinline__ void ldsm_x4t(uint32_t& r0, uint32_t& r1, uint32_t& r2,
                                         uint32_t& r3, uint32_t addr) {
    asm volatile("ldmatrix.sync.aligned.m8n8.x4.trans.shared.b16 {%0,%1,%2,%3}, [%4];"
                 : "=r"(r0), "=r"(r1), "=r"(r2), "=r"(r3) : "r"(addr));
}
__device__ __forceinline__ void mma16816(float* c, const uint32_t* a, const uint32_t* b) {
    asm volatile("mma.sync.aligned.m16n8k16.row.col.f32.f16.f16.f32 "
                 "{%0,%1,%2,%3}, {%4,%5,%6,%7}, {%8,%9}, {%0,%1,%2,%3};"
                 : "+f"(c[0]), "+f"(c[1]), "+f"(c[2]), "+f"(c[3])
                 : "r"(a[0]), "r"(a[1]), "r"(a[2]), "r"(a[3]), "r"(b[0]), "r"(b[1]));
}

// ---------------- quant kernels ---------------------------------------------
__global__ void k_init() {
    int t = threadIdx.x;
    if (t < 128) { g_counts[0][t] = 0; g_counts[1][t] = 0; }
    if (t == 0) {
        g_minkey = 0xFFFFFFFFu; g_maxkey = 0u;
        g_dmax[0] = 0.0f; g_dmax[1] = 0.0f;
    }
}

// fused: global minmax of U + x -> fp16 conversion (independent streams of work)
__global__ void __launch_bounds__(256) k_minmax_xhalf(const float* __restrict__ U,
                                                      const float* __restrict__ x) {
    int gtid = blockIdx.x * blockDim.x + threadIdx.x;
    int stride = gridDim.x * blockDim.x;

    // part 1: x -> fp16
    for (int v = gtid; v < XELEMS / 4; v += stride) {
        float4 a = ((const float4*)x)[v];
        __half2 p0 = __floats2half2_rn(a.x, a.y);
        __half2 p1 = __floats2half2_rn(a.z, a.w);
        uint2 pk;
        pk.x = *reinterpret_cast<uint32_t*>(&p0);
        pk.y = *reinterpret_cast<uint32_t*>(&p1);
        *(uint2*)(&g_xh[(size_t)v * 4]) = pk;
    }

    // part 2: minmax over U
    float lmin = 3.4e38f, lmax = -3.4e38f;
    const float4* U4 = (const float4*)U;
    for (int i = gtid * 2; i < (NROW * DCOLS) / 4; i += stride * 2) {
        float4 v0 = U4[i];
        float4 v1 = U4[i + 1];
        lmin = fminf(lmin, fminf(fminf(v0.x, v0.y), fminf(v0.z, v0.w)));
        lmax = fmaxf(lmax, fmaxf(fmaxf(v0.x, v0.y), fmaxf(v0.z, v0.w)));
        lmin = fminf(lmin, fminf(fminf(v1.x, v1.y), fminf(v1.z, v1.w)));
        lmax = fmaxf(lmax, fmaxf(fmaxf(v1.x, v1.y), fmaxf(v1.z, v1.w)));
    }
#pragma unroll
    for (int o = 16; o; o >>= 1) {
        lmin = fminf(lmin, __shfl_xor_sync(0xffffffffu, lmin, o));
        lmax = fmaxf(lmax, __shfl_xor_sync(0xffffffffu, lmax, o));
    }
    __shared__ float smn[8], smx[8];
    int w = threadIdx.x >> 5;
    if ((threadIdx.x & 31) == 0) { smn[w] = lmin; smx[w] = lmax; }
    __syncthreads();
    if (threadIdx.x == 0) {
        float a = smn[0], b = smx[0];
        for (int q = 1; q < 8; q++) { a = fminf(a, smn[q]); b = fmaxf(b, smx[q]); }
        atomicMin(&g_minkey, fencode(a));
        atomicMax(&g_maxkey, fencode(b));
    }
}

__global__ void __launch_bounds__(256) k_scales(const float* __restrict__ tm) {
    int t = blockIdx.x * 256 + threadIdx.x;
    if (t < 1024) g_thr[t] = sigm(tm[t]);
    if (t == 0) {
        float mn = fdecode(g_minkey), mx = fdecode(g_maxkey);
        float s0 = __fdiv_rn(mx - mn, 3.0f);
        float s1 = __fdiv_rn(s0, 5.0f);
        float s2 = __fdiv_rn(s1, 17.0f);
        g_s[0] = s0; g_s[1] = s1; g_s[2] = s2;
        g_sinv[0] = __fdiv_rn(1.0f, s0);
        g_sinv[1] = __fdiv_rn(1.0f, s1);
        g_sinv[2] = __fdiv_rn(1.0f, s2);
    }
}

// deltamax0: 2 columns per thread (proven-best R12 config)
__global__ void __launch_bounds__(256) k_deltamax0(const float* __restrict__ U) {
    int j2 = (blockIdx.x * 256 + threadIdx.x) * 2;
    float s0 = g_s[0], is0 = g_sinv[0];
    float ra[8], rb[8];
#pragma unroll
    for (int i = 0; i < 8; i++) {
        float2 u = *(const float2*)&U[(size_t)i * DCOLS + j2];
        ra[i] = u.x - s0 * floorf(u.x * is0);
        rb[i] = u.y - s0 * floorf(u.y * is0);
    }
    sortf8(ra);
    sortf8(rb);
    float m = fmaxf(delta_max7(ra), delta_max7(rb));
#pragma unroll
    for (int o = 16; o; o >>= 1) m = fmaxf(m, __shfl_xor_sync(0xffffffffu, m, o));
    __shared__ float sm[8];
    int w = threadIdx.x >> 5;
    if ((threadIdx.x & 31) == 0) sm[w] = m;
    __syncthreads();
    if (threadIdx.x == 0) {
        float mm = sm[0];
        for (int q = 1; q < 8; q++) mm = fmaxf(mm, sm[q]);
        atomicMax((int*)&g_dmax[0], __float_as_int(mm));
    }
}

// histogram: 2 columns per thread; lvl1 reads U + lattice codes
__global__ void __launch_bounds__(256) k_hist(const float* __restrict__ U, int lvl) {
    __shared__ int h[128];
    if (threadIdx.x < 128) h[threadIdx.x] = 0;
    __syncthreads();
    int j2 = (blockIdx.x * 256 + threadIdx.x) * 2;
    float s0 = g_s[0], is0 = g_sinv[0];
    float ra[8], rb[8];
    if (lvl == 0) {
#pragma unroll
        for (int i = 0; i < 8; i++) {
            float2 u = *(const float2*)&U[(size_t)i * DCOLS + j2];
            ra[i] = u.x - s0 * floorf(u.x * is0);
            rb[i] = u.y - s0 * floorf(u.y * is0);
        }
    } else {
        float s1 = g_s[1];
#pragma unroll
        for (int i = 0; i < 8; i++) {
            float2 u = *(const float2*)&U[(size_t)i * DCOLS + j2];
            uchar2 c = *(const uchar2*)&g_code[(size_t)i * DCOLS + j2];
            ra[i] = u.x - decode_nv(c.x, s0, s1);
            rb[i] = u.y - decode_nv(c.y, s0, s1);
        }
    }
    sortf8(ra);
    sortf8(rb);
    float dmax = g_dmax[lvl];
    float tda = g_thr[j2 >> 11] * dmax;
    float tdb = g_thr[(j2 + 1) >> 11] * dmax;
    atomicAdd(&h[column_code_fast(ra, tda)], 1);
    atomicAdd(&h[column_code_fast(rb, tdb)], 1);
    __syncthreads();
    if (threadIdx.x < 128 && h[threadIdx.x])
        atomicAdd(&g_counts[lvl][threadIdx.x], h[threadIdx.x]);
}

__global__ void __launch_bounds__(128) k_finalize(const float* __restrict__ U, int lvl) {
    __shared__ int cnts[128], rnk[128], tcode[5], trank[5];
    int p = threadIdx.x;
    cnts[p] = g_counts[lvl][p];
    __syncthreads();
    if (p == 0) {
        int r = 0;
        for (int q = 0; q < 128; q++) { rnk[q] = r; if (cnts[q] > 0) r++; }
        bool used[128];
        for (int q = 0; q < 128; q++) used[q] = false;
        for (int t = 0; t < 5; t++) {
            int best = -1, bc = -1;
            for (int q = 0; q < 128; q++)
                if (!used[q] && cnts[q] > bc) { bc = cnts[q]; best = q; }
            used[best] = true;
            tcode[t] = best; trank[t] = rnk[best];
        }
    }
    __syncthreads();
    int bestT = 0, bestV = -1;
#pragma unroll
    for (int t = 0; t < 5; t++) {
        int iv = __popc(p & tcode[t]);
        if (iv > bestV) { bestV = iv; bestT = t; }
    }
    bool istop = false;
#pragma unroll
    for (int t = 0; t < 5; t++) istop |= (rnk[p] == trank[t]);
    g_rank_lut[p] = istop ? rnk[p] : trank[bestT];

    // msp / rs table for data columns 0..127 (exact sigmoid math)
    float r[8];
    float s0 = g_s[0], is0 = g_sinv[0];
    if (lvl == 0) {
#pragma unroll
        for (int i = 0; i < 8; i++) {
            float u = U[(size_t)i * DCOLS + p];
            r[i] = u - s0 * floorf(u * is0);
        }
    } else {
        float s1 = g_s[1];
#pragma unroll
        for (int i = 0; i < 8; i++) {
            float u = U[(size_t)i * DCOLS + p];
            r[i] = u - decode_nv(g_code[(size_t)i * DCOLS + p], s0, s1);
        }
    }
    sortf8(r);
    float dmax = g_dmax[lvl];
    float thr  = g_thr[p >> 11];
    unsigned char bits = 0;
#pragma unroll
    for (int i = 0; i < 7; i++) {
        float d  = r[i + 1] - r[i];
        float z  = __fdiv_rn(__fdiv_rn(d, dmax) - thr, 0.01f);
        float mv = sigm(z);
        g_msp_tab[i * 128 + p] = mv;
        if ((int)rintf(mv)) bits |= (unsigned char)(1u << i);
    }
    g_rs_tab[p] = bits;
}

// update lvl0: stores lattice codes + fused deltamax1. lvl1: writes W fp16.
// Packed u32 sort (idx in low 3 bits) + smem scatter for inverse permutation.
__global__ void __launch_bounds__(256) k_update(const float* __restrict__ U, int lvl) {
    __shared__ float scat[256 * 9];
    int tid = threadIdx.x;
    int j = blockIdx.x * 256 + tid;
    float s0 = g_s[0], is0 = g_sinv[0], s1 = g_s[1];
    float uv[8], vs[8], r[8];
    float k0f[8];
    if (lvl == 0) {
#pragma unroll
        for (int i = 0; i < 8; i++) {
            uv[i] = U[(size_t)i * DCOLS + j];
            k0f[i] = floorf(uv[i] * is0);
            vs[i] = s0 * k0f[i];
            r[i] = uv[i] - vs[i];
        }
    } else {
#pragma unroll
        for (int i = 0; i < 8; i++) {
            uv[i] = U[(size_t)i * DCOLS + j];
            vs[i] = decode_nv(g_code[(size_t)i * DCOLS + j], s0, s1);
            r[i] = uv[i] - vs[i];
        }
    }
    unsigned key[8];
#pragma unroll
    for (int i = 0; i < 8; i++) key[i] = (fencode(r[i]) & 0xFFFFFFF8u) | (unsigned)i;
    sortu8(key);
    float sv[8];
#pragma unroll
    for (int k = 0; k < 8; k++) sv[k] = fdecode(key[k] & 0xFFFFFFF8u);

    float dmax = g_dmax[lvl];
    float td = g_thr[j >> 11] * dmax;
    int code = column_code_fast(sv, td);
    int cr = g_rank_lut[code];
    unsigned sb = g_rs_tab[cr];
    float s = g_s[1 + lvl], is = g_sinv[1 + lvl];

    float buf = 0.0f, cnt = 0.0f, g = 1.0f;
    bool reset = false;
    float v[8]; unsigned bl = 0;
#pragma unroll
    for (int i = 0; i < 8; i++) {
        if (reset) { buf = sv[i]; cnt = 1.0f; g = 1.0f; }
        else       { buf += sv[i]; cnt += 1.0f; }
        float mean = __fdividef(buf, cnt);
        if (i == 7) v[7] = g * mean;
        else {
            bool b = (sb >> i) & 1u;
            float mu = g_msp_tab[i * 128 + cr];
            v[i] = b ? (g * mu) * mean : 0.0f;
            if (b) bl |= (1u << i);
            else   g = g * (1.0f - mu);
            reset = b;
        }
    }
    int base = tid * 9;
    {
        float cur = v[7];
        scat[base + (key[7] & 7u)] = cur;
#pragma unroll
        for (int i = 6; i >= 0; i--) {
            if ((bl >> i) & 1u) cur = v[i];
            scat[base + (key[i] & 7u)] = cur;
        }
    }
    if (lvl == 0) {
        float r1[8];
#pragma unroll
        for (int i = 0; i < 8; i++) {
            float gi = scat[base + i];
            float k1f = floorf(gi * is);
            float nv = vs[i] + s * k1f;
            r1[i] = uv[i] - nv;
            int k0i = (int)k0f[i] + 8;
            int k1i = (int)k1f + 2;
            g_code[(size_t)i * DCOLS + j] = (unsigned char)((k0i & 15) | (k1i << 4));
        }
        sortf8(r1);
        float m = delta_max7(r1);
#pragma unroll
        for (int o = 16; o; o >>= 1) m = fmaxf(m, __shfl_xor_sync(0xffffffffu, m, o));
        __shared__ float sm[8];
        int w = tid >> 5;
        if ((tid & 31) == 0) sm[w] = m;
        __syncthreads();
        if (tid == 0) {
            float mm = sm[0];
            for (int q = 1; q < 8; q++) mm = fmaxf(mm, sm[q]);
            atomicMax((int*)&g_dmax[1], __float_as_int(mm));
        }
    } else {
#pragma unroll
        for (int i = 0; i < 8; i++) {
            float gi = scat[base + i];
            float nv = vs[i] + s * floorf(gi * is);
            g_wh[(size_t)i * DCOLS + j] = __float2half_rn(nv);
        }
    }
}

// ---------------- HMMA GEMM (fp16, full-K, 3-stage cp.async) ----------------
#define GEMM_SMEM (3 * 32768)
#define BSWZ(k, cbyte) ((uint32_t)((k) * 256 + (cbyte)) ^ ((uint32_t)((k) & 7) << 4))
#define KTILES 32

__global__ void __launch_bounds__(256, 2) k_gemm(float* __restrict__ out) {
    extern __shared__ char smemraw[];
    uint32_t smb = smem_u32(smemraw);
    int tid = threadIdx.x, wid = tid >> 5, lane = tid & 31;
    int e = blockIdx.z, bm = blockIdx.y * 128, bn = blockIdx.x * 128;

    const __half* A = g_xh + (size_t)e * 2048  + (size_t)bm * 16384;
    const __half* B = g_wh + (size_t)e * DCOLS + bn;

    uint32_t aswz[4], bswz[4];
    size_t aofs[4], bofs[4];
#pragma unroll
    for (int i = 0; i < 4; i++) {
        int v = tid + i * 256;
        int arow = v >> 3, ac = v & 7;
        aswz[i] = SWZ128((uint32_t)(arow * 128 + ac * 16));
        aofs[i] = (size_t)arow * 16384 + ac * 8;
        int brow = v >> 4, bc = v & 15;
        bswz[i] = BSWZ(brow, bc * 16);
        bofs[i] = (size_t)brow * 1024 + bc * 8;
    }

    int wm = (wid & 1) * 64, wn = (wid >> 1) * 32;
    int a_row = lane & 15;
    int a_kb  = (lane >> 4) * 16;
    int b_krb = (lane & 7) + ((lane >> 3) & 1) * 8;
    int b_nch = (lane >> 4) * 8;

    float c[4][4][4];
#pragma unroll
    for (int mi = 0; mi < 4; mi++)
#pragma unroll
        for (int ni = 0; ni < 4; ni++)
#pragma unroll
            for (int q = 0; q < 4; q++) c[mi][ni][q] = 0.0f;

#pragma unroll
    for (int t = 0; t < 2; t++) {
        uint32_t base = smb + t * 32768;
        int k0 = t * 64;
#pragma unroll
        for (int i = 0; i < 4; i++) {
            CP_ASYNC16(base + aswz[i],         A + aofs[i] + k0);
            CP_ASYNC16(base + 16384 + bswz[i], B + bofs[i] + (size_t)k0 * 1024);
        }
        CP_COMMIT();
    }

#pragma unroll 1
    for (int t = 0; t < KTILES; t++) {
        if (t == KTILES - 1) { CP_WAIT(0); } else { CP_WAIT(1); }
        __syncthreads();
        if (t + 2 < KTILES) {
            uint32_t base = smb + ((t + 2) % 3) * 32768;
            int k0 = (t + 2) * 64;
#pragma unroll
            for (int i = 0; i < 4; i++) {
                CP_ASYNC16(base + aswz[i],         A + aofs[i] + k0);
                CP_ASYNC16(base + 16384 + bswz[i], B + bofs[i] + (size_t)k0 * 1024);
            }
            CP_COMMIT();
        }

        uint32_t base = smb + (t % 3) * 32768;
#pragma unroll
        for (int ks = 0; ks < 4; ks++) {
            uint32_t a[4][4], b[4][2];
#pragma unroll
            for (int mi = 0; mi < 4; mi++) {
                int row = wm + mi * 16 + a_row;
                uint32_t off = SWZ128((uint32_t)(row * 128 + ks * 32 + a_kb));
                ldsm_x4(a[mi][0], a[mi][1], a[mi][2], a[mi][3], base + off);
            }
#pragma unroll
            for (int np = 0; np < 2; np++) {
                int k_row = ks * 16 + b_krb;
                int n_col = wn + np * 16 + b_nch;
                uint32_t off = BSWZ(k_row, (n_col >> 3) << 4);
                uint32_t r0, r1, r2, r3;
                ldsm_x4t(r0, r1, r2, r3, base + 16384 + off);
                b[np * 2][0] = r0; b[np * 2][1] = r1;
                b[np * 2 + 1][0] = r2; b[np * 2 + 1][1] = r3;
            }
#pragma unroll
            for (int mi = 0; mi < 4; mi++)
#pragma unroll
                for (int ni = 0; ni < 4; ni++)
                    mma16816(c[mi][ni], a[mi], b[ni]);
        }
    }

    int group = lane >> 2, tig = lane & 3;
#pragma unroll
    for (int mi = 0; mi < 4; mi++) {
        int m0 = bm + wm + mi * 16 + group;
#pragma unroll
        for (int ni = 0; ni < 4; ni++) {
            int n0 = bn + wn + ni * 8 + tig * 2;
            float2 v0 = make_float2(c[mi][ni][0], c[mi][ni][1]);
            float2 v1 = make_float2(c[mi][ni][2], c[mi][ni][3]);
            *(float2*)(out + (size_t)m0 * 8192 + (size_t)e * 1024 + n0)       = v0;
            *(float2*)(out + (size_t)(m0 + 8) * 8192 + (size_t)e * 1024 + n0) = v1;
        }
    }
}

// ---------------- launch ----------------------------------------------------
extern "C" void kernel_launch(void* const* d_in, const int* in_sizes, int n_in,
                              void* d_out, int out_size) {
    const float* x = nullptr; const float* U = nullptr; const float* tm = nullptr;
    for (int i = 0; i < n_in; i++) {
        if (in_sizes[i] == NROW * DCOLS)      U  = (const float*)d_in[i];
        else if (in_sizes[i] == XELEMS)       x  = (const float*)d_in[i];
        else if (in_sizes[i] == DD2)          tm = (const float*)d_in[i];
    }
    float* out = (float*)d_out;

    cudaFuncSetAttribute(k_gemm, cudaFuncAttributeMaxDynamicSharedMemorySize, GEMM_SMEM);

    k_init<<<1, 256>>>();
    k_minmax_xhalf<<<2048, 256>>>(U, x);
    k_scales<<<4, 256>>>(tm);

    k_deltamax0<<<DCOLS / 512, 256>>>(U);
    k_hist<<<DCOLS / 512, 256>>>(U, 0);
    k_finalize<<<1, 128>>>(U, 0);
    k_update<<<DCOLS / 256, 256>>>(U, 0);      // stores lattice codes, fused deltamax1

    k_hist<<<DCOLS / 512, 256>>>(U, 1);
    k_finalize<<<1, 128>>>(U, 1);
    k_update<<<DCOLS / 256, 256>>>(U, 1);      // writes W fp16 directly

    dim3 gg(DD2 / 128, NBATCH / 128, NROW);
    k_gemm<<<gg, 256, GEMM_SMEM>>>(out);
}

// round 16
// speedup vs baseline: 1.0505x; 1.0505x over previous
#include <cuda_runtime.h>
#include <cuda_fp16.h>
#include <math.h>
#include <stdint.h>

#define NROW   8
#define DCOLS  2097152
#define DD1    2048
#define DD2    1024
#define NBATCH 512
#define XELEMS (NBATCH * NROW * DD1)   // 8388608

// ---------------- scratch (static device globals; no allocations) ----------
__device__ unsigned char g_code[NROW * DCOLS];   // 16 MB: lattice codes (k0,k1) for vsum1
__device__ __half        g_wh[NROW * DCOLS];     // 16 MB  W fp16, natural [e][k][n]
__device__ __half        g_xh[XELEMS];           // 16 MB  x fp16
__device__ unsigned      g_minkey, g_maxkey;
__device__ float         g_s[3];                 // s0, s1, s2
__device__ float         g_sinv[3];              // 1/s0, 1/s1, 1/s2
__device__ float         g_thr[1024];            // sigm(thres_mean)
__device__ float         g_dmax[2];
__device__ int           g_counts[2][128];
__device__ int           g_rank_lut[128];
__device__ float         g_msp_tab[7 * 128];
__device__ unsigned char g_rs_tab[128];

// ---------------- helpers ---------------------------------------------------
__device__ __forceinline__ unsigned fencode(float f) {
    unsigned u = __float_as_uint(f);
    unsigned m = (unsigned)((int)u >> 31);
    return u ^ (m | 0x80000000u);
}
__device__ __forceinline__ float fdecode(unsigned k) {
    unsigned u = (k & 0x80000000u) ? (k ^ 0x80000000u) : ~k;
    return __uint_as_float(u);
}
__device__ __forceinline__ float sigm(float x) {
    return __fdiv_rn(1.0f, 1.0f + expf(-x));
}
__device__ __forceinline__ float decode_nv(unsigned char b, float s0, float s1) {
    float k0 = (float)((int)(b & 15u) - 8);
    float k1 = (float)((int)(b >> 4) - 2);
    return s0 * k0 + s1 * k1;
}

// value-only sort: fmin/fmax CE network directly on floats
__device__ __forceinline__ void sortf8(float a[8]) {
#define CEF(i, j) { float _lo = fminf(a[i], a[j]); float _hi = fmaxf(a[i], a[j]); a[i] = _lo; a[j] = _hi; }
    CEF(0,1) CEF(2,3) CEF(4,5) CEF(6,7)
    CEF(0,2) CEF(1,3) CEF(4,6) CEF(5,7)
    CEF(1,2) CEF(5,6) CEF(0,4) CEF(3,7)
    CEF(1,5) CEF(2,6)
    CEF(1,4) CEF(3,6)
    CEF(2,4) CEF(3,5)
    CEF(3,4)
#undef CEF
}
// packed u32 sort (index in low 3 bits)
__device__ __forceinline__ void sortu8(unsigned a[8]) {
#define CEU(i, j) { unsigned _lo = min(a[i], a[j]); unsigned _hi = max(a[i], a[j]); a[i] = _lo; a[j] = _hi; }
    CEU(0,1) CEU(2,3) CEU(4,5) CEU(6,7)
    CEU(0,2) CEU(1,3) CEU(4,6) CEU(5,7)
    CEU(1,2) CEU(5,6) CEU(0,4) CEU(3,7)
    CEU(1,5) CEU(2,6)
    CEU(1,4) CEU(3,6)
    CEU(2,4) CEU(3,5)
    CEU(3,4)
#undef CEU
}

__device__ __forceinline__ int column_code_fast(const float sv[8], float thr_dmax) {
    int code = 0;
#pragma unroll
    for (int i = 0; i < 7; i++)
        code = (code << 1) | ((sv[i + 1] - sv[i]) > thr_dmax ? 1 : 0);
    return code;
}
__device__ __forceinline__ float delta_max7(const float sv[8]) {
    float m = 0.0f;
#pragma unroll
    for (int i = 0; i < 7; i++) m = fmaxf(m, sv[i + 1] - sv[i]);
    return m;
}

// ---------------- PTX helpers -------------------------------------------------
__device__ __forceinline__ uint32_t smem_u32(const void* p) {
    uint32_t a;
    asm("{ .reg .u64 t; cvta.to.shared.u64 t, %1; cvt.u32.u64 %0, t; }" : "=r"(a) : "l"(p));
    return a;
}
#define CP_ASYNC16(dst, src) \
    asm volatile("cp.async.cg.shared.global [%0], [%1], 16;" :: "r"(dst), "l"(src))
#define CP_COMMIT() asm volatile("cp.async.commit_group;" ::: "memory")
#define CP_WAIT(n)  asm volatile("cp.async.wait_group %0;" :: "n"(n) : "memory")
#define SWZ128(b)   ((b) ^ (((b) >> 3) & 0x70))

__device__ __forceinline__ void ldsm_x4(uint32_t& r0, uint32_t& r1, uint32_t& r2,
                                        uint32_t& r3, uint32_t addr) {
    asm volatile("ldmatrix.sync.aligned.m8n8.x4.shared.b16 {%0,%1,%2,%3}, [%4];"
                 : "=r"(r0), "=r"(r1), "=r"(r2), "=r"(r3) : "r"(addr));
}
__device__ __forceinline__ void ldsm_x4t(uint32_t& r0, uint32_t& r1, uint32_t& r2,
                                         uint32_t& r3, uint32_t addr) {
    asm volatile("ldmatrix.sync.aligned.m8n8.x4.trans.shared.b16 {%0,%1,%2,%3}, [%4];"
                 : "=r"(r0), "=r"(r1), "=r"(r2), "=r"(r3) : "r"(addr));
}
__device__ __forceinline__ void mma16816(float* c, const uint32_t* a, const uint32_t* b) {
    asm volatile("mma.sync.aligned.m16n8k16.row.col.f32.f16.f16.f32 "
                 "{%0,%1,%2,%3}, {%4,%5,%6,%7}, {%8,%9}, {%0,%1,%2,%3};"
                 : "+f"(c[0]), "+f"(c[1]), "+f"(c[2]), "+f"(c[3])
                 : "r"(a[0]), "r"(a[1]), "r"(a[2]), "r"(a[3]), "r"(b[0]), "r"(b[1]));
}

// ---------------- quant kernels ---------------------------------------------
__global__ void k_init() {
    int t = threadIdx.x;
    if (t < 128) { g_counts[0][t] = 0; g_counts[1][t] = 0; }
    if (t == 0) {
        g_minkey = 0xFFFFFFFFu; g_maxkey = 0u;
        g_dmax[0] = 0.0f; g_dmax[1] = 0.0f;
    }
}

// fused: global minmax of U + x -> fp16 conversion
__global__ void __launch_bounds__(256) k_minmax_xhalf(const float* __restrict__ U,
                                                      const float* __restrict__ x) {
    int gtid = blockIdx.x * blockDim.x + threadIdx.x;
    int stride = gridDim.x * blockDim.x;

    for (int v = gtid; v < XELEMS / 4; v += stride) {
        float4 a = ((const float4*)x)[v];
        __half2 p0 = __floats2half2_rn(a.x, a.y);
        __half2 p1 = __floats2half2_rn(a.z, a.w);
        uint2 pk;
        pk.x = *reinterpret_cast<uint32_t*>(&p0);
        pk.y = *reinterpret_cast<uint32_t*>(&p1);
        *(uint2*)(&g_xh[(size_t)v * 4]) = pk;
    }

    float lmin = 3.4e38f, lmax = -3.4e38f;
    const float4* U4 = (const float4*)U;
    for (int i = gtid * 2; i < (NROW * DCOLS) / 4; i += stride * 2) {
        float4 v0 = U4[i];
        float4 v1 = U4[i + 1];
        lmin = fminf(lmin, fminf(fminf(v0.x, v0.y), fminf(v0.z, v0.w)));
        lmax = fmaxf(lmax, fmaxf(fmaxf(v0.x, v0.y), fmaxf(v0.z, v0.w)));
        lmin = fminf(lmin, fminf(fminf(v1.x, v1.y), fminf(v1.z, v1.w)));
        lmax = fmaxf(lmax, fmaxf(fmaxf(v1.x, v1.y), fmaxf(v1.z, v1.w)));
    }
#pragma unroll
    for (int o = 16; o; o >>= 1) {
        lmin = fminf(lmin, __shfl_xor_sync(0xffffffffu, lmin, o));
        lmax = fmaxf(lmax, __shfl_xor_sync(0xffffffffu, lmax, o));
    }
    __shared__ float smn[8], smx[8];
    int w = threadIdx.x >> 5;
    if ((threadIdx.x & 31) == 0) { smn[w] = lmin; smx[w] = lmax; }
    __syncthreads();
    if (threadIdx.x == 0) {
        float a = smn[0], b = smx[0];
        for (int q = 1; q < 8; q++) { a = fminf(a, smn[q]); b = fmaxf(b, smx[q]); }
        atomicMin(&g_minkey, fencode(a));
        atomicMax(&g_maxkey, fencode(b));
    }
}

__global__ void __launch_bounds__(256) k_scales(const float* __restrict__ tm) {
    int t = blockIdx.x * 256 + threadIdx.x;
    if (t < 1024) g_thr[t] = sigm(tm[t]);
    if (t == 0) {
        float mn = fdecode(g_minkey), mx = fdecode(g_maxkey);
        float s0 = __fdiv_rn(mx - mn, 3.0f);
        float s1 = __fdiv_rn(s0, 5.0f);
        float s2 = __fdiv_rn(s1, 17.0f);
        g_s[0] = s0; g_s[1] = s1; g_s[2] = s2;
        g_sinv[0] = __fdiv_rn(1.0f, s0);
        g_sinv[1] = __fdiv_rn(1.0f, s1);
        g_sinv[2] = __fdiv_rn(1.0f, s2);
    }
}

// deltamax0: 2 columns per thread (proven-best: 32 regs, 85% occ)
__global__ void __launch_bounds__(256) k_deltamax0(const float* __restrict__ U) {
    int j2 = (blockIdx.x * 256 + threadIdx.x) * 2;
    float s0 = g_s[0], is0 = g_sinv[0];
    float ra[8], rb[8];
#pragma unroll
    for (int i = 0; i < 8; i++) {
        float2 u = *(const float2*)&U[(size_t)i * DCOLS + j2];
        ra[i] = u.x - s0 * floorf(u.x * is0);
        rb[i] = u.y - s0 * floorf(u.y * is0);
    }
    sortf8(ra);
    sortf8(rb);
    float m = fmaxf(delta_max7(ra), delta_max7(rb));
#pragma unroll
    for (int o = 16; o; o >>= 1) m = fmaxf(m, __shfl_xor_sync(0xffffffffu, m, o));
    __shared__ float sm[8];
    int w = threadIdx.x >> 5;
    if ((threadIdx.x & 31) == 0) sm[w] = m;
    __syncthreads();
    if (threadIdx.x == 0) {
        float mm = sm[0];
        for (int q = 1; q < 8; q++) mm = fmaxf(mm, sm[q]);
        atomicMax((int*)&g_dmax[0], __float_as_int(mm));
    }
}

// histogram: 4 columns per thread, float4/uchar4 loads (R14's measured-fast form)
__global__ void __launch_bounds__(256) k_hist(const float* __restrict__ U, int lvl) {
    __shared__ int h[128];
    if (threadIdx.x < 128) h[threadIdx.x] = 0;
    __syncthreads();
    int j4 = (blockIdx.x * 256 + threadIdx.x) * 4;
    float s0 = g_s[0], is0 = g_sinv[0], s1 = g_s[1];
    float4 uraw[8];
    uchar4 craw[8];
#pragma unroll
    for (int i = 0; i < 8; i++)
        uraw[i] = *(const float4*)&U[(size_t)i * DCOLS + j4];
    if (lvl != 0) {
#pragma unroll
        for (int i = 0; i < 8; i++)
            craw[i] = *(const uchar4*)&g_code[(size_t)i * DCOLS + j4];
    }
    float dmax = g_dmax[lvl];
#pragma unroll
    for (int q = 0; q < 4; q++) {
        float r[8];
#pragma unroll
        for (int i = 0; i < 8; i++) {
            float u = (q == 0) ? uraw[i].x : (q == 1) ? uraw[i].y : (q == 2) ? uraw[i].z : uraw[i].w;
            if (lvl == 0) {
                r[i] = u - s0 * floorf(u * is0);
            } else {
                unsigned char c = (q == 0) ? craw[i].x : (q == 1) ? craw[i].y : (q == 2) ? craw[i].z : craw[i].w;
                r[i] = u - decode_nv(c, s0, s1);
            }
        }
        sortf8(r);
        float td = g_thr[(j4 + q) >> 11] * dmax;
        atomicAdd(&h[column_code_fast(r, td)], 1);
    }
    __syncthreads();
    if (threadIdx.x < 128 && h[threadIdx.x])
        atomicAdd(&g_counts[lvl][threadIdx.x], h[threadIdx.x]);
}

__global__ void __launch_bounds__(128) k_finalize(const float* __restrict__ U, int lvl) {
    __shared__ int cnts[128], rnk[128], tcode[5], trank[5];
    int p = threadIdx.x;
    cnts[p] = g_counts[lvl][p];
    __syncthreads();
    if (p == 0) {
        int r = 0;
        for (int q = 0; q < 128; q++) { rnk[q] = r; if (cnts[q] > 0) r++; }
        bool used[128];
        for (int q = 0; q < 128; q++) used[q] = false;
        for (int t = 0; t < 5; t++) {
            int best = -1, bc = -1;
            for (int q = 0; q < 128; q++)
                if (!used[q] && cnts[q] > bc) { bc = cnts[q]; best = q; }
            used[best] = true;
            tcode[t] = best; trank[t] = rnk[best];
        }
    }
    __syncthreads();
    int bestT = 0, bestV = -1;
#pragma unroll
    for (int t = 0; t < 5; t++) {
        int iv = __popc(p & tcode[t]);
        if (iv > bestV) { bestV = iv; bestT = t; }
    }
    bool istop = false;
#pragma unroll
    for (int t = 0; t < 5; t++) istop |= (rnk[p] == trank[t]);
    g_rank_lut[p] = istop ? rnk[p] : trank[bestT];

    float r[8];
    float s0 = g_s[0], is0 = g_sinv[0];
    if (lvl == 0) {
#pragma unroll
        for (int i = 0; i < 8; i++) {
            float u = U[(size_t)i * DCOLS + p];
            r[i] = u - s0 * floorf(u * is0);
        }
    } else {
        float s1 = g_s[1];
#pragma unroll
        for (int i = 0; i < 8; i++) {
            float u = U[(size_t)i * DCOLS + p];
            r[i] = u - decode_nv(g_code[(size_t)i * DCOLS + p], s0, s1);
        }
    }
    sortf8(r);
    float dmax = g_dmax[lvl];
    float thr  = g_thr[p >> 11];
    unsigned char bits = 0;
#pragma unroll
    for (int i = 0; i < 7; i++) {
        float d  = r[i + 1] - r[i];
        float z  = __fdiv_rn(__fdiv_rn(d, dmax) - thr, 0.01f);
        float mv = sigm(z);
        g_msp_tab[i * 128 + p] = mv;
        if ((int)rintf(mv)) bits |= (unsigned char)(1u << i);
    }
    g_rs_tab[p] = bits;
}

// update lvl0: stores lattice codes + fused deltamax1. lvl1: writes W fp16.
__global__ void __launch_bounds__(256) k_update(const float* __restrict__ U, int lvl) {
    __shared__ float scat[256 * 9];
    int tid = threadIdx.x;
    int j = blockIdx.x * 256 + tid;
    float s0 = g_s[0], is0 = g_sinv[0], s1 = g_s[1];
    float uv[8], vs[8], r[8];
    float k0f[8];
    if (lvl == 0) {
#pragma unroll
        for (int i = 0; i < 8; i++) {
            uv[i] = U[(size_t)i * DCOLS + j];
            k0f[i] = floorf(uv[i] * is0);
            vs[i] = s0 * k0f[i];
            r[i] = uv[i] - vs[i];
        }
    } else {
#pragma unroll
        for (int i = 0; i < 8; i++) {
            uv[i] = U[(size_t)i * DCOLS + j];
            vs[i] = decode_nv(g_code[(size_t)i * DCOLS + j], s0, s1);
            r[i] = uv[i] - vs[i];
        }
    }
    unsigned key[8];
#pragma unroll
    for (int i = 0; i < 8; i++) key[i] = (fencode(r[i]) & 0xFFFFFFF8u) | (unsigned)i;
    sortu8(key);
    float sv[8];
#pragma unroll
    for (int k = 0; k < 8; k++) sv[k] = fdecode(key[k] & 0xFFFFFFF8u);

    float dmax = g_dmax[lvl];
    float td = g_thr[j >> 11] * dmax;
    int code = column_code_fast(sv, td);
    int cr = g_rank_lut[code];
    unsigned sb = g_rs_tab[cr];
    float s = g_s[1 + lvl], is = g_sinv[1 + lvl];

    float buf = 0.0f, cnt = 0.0f, g = 1.0f;
    bool reset = false;
    float v[8]; unsigned bl = 0;
#pragma unroll
    for (int i = 0; i < 8; i++) {
        if (reset) { buf = sv[i]; cnt = 1.0f; g = 1.0f; }
        else       { buf += sv[i]; cnt += 1.0f; }
        float mean = __fdividef(buf, cnt);
        if (i == 7) v[7] = g * mean;
        else {
            bool b = (sb >> i) & 1u;
            float mu = g_msp_tab[i * 128 + cr];
            v[i] = b ? (g * mu) * mean : 0.0f;
            if (b) bl |= (1u << i);
            else   g = g * (1.0f - mu);
            reset = b;
        }
    }
    int base = tid * 9;
    {
        float cur = v[7];
        scat[base + (key[7] & 7u)] = cur;
#pragma unroll
        for (int i = 6; i >= 0; i--) {
            if ((bl >> i) & 1u) cur = v[i];
            scat[base + (key[i] & 7u)] = cur;
        }
    }
    if (lvl == 0) {
        float r1[8];
#pragma unroll
        for (int i = 0; i < 8; i++) {
            float gi = scat[base + i];
            float k1f = floorf(gi * is);
            float nv = vs[i] + s * k1f;
            r1[i] = uv[i] - nv;
            int k0i = (int)k0f[i] + 8;
            int k1i = (int)k1f + 2;
            g_code[(size_t)i * DCOLS + j] = (unsigned char)((k0i & 15) | (k1i << 4));
        }
        sortf8(r1);
        float m = delta_max7(r1);
#pragma unroll
        for (int o = 16; o; o >>= 1) m = fmaxf(m, __shfl_xor_sync(0xffffffffu, m, o));
        __shared__ float sm[8];
        int w = tid >> 5;
        if ((tid & 31) == 0) sm[w] = m;
        __syncthreads();
        if (tid == 0) {
            float mm = sm[0];
            for (int q = 1; q < 8; q++) mm = fmaxf(mm, sm[q]);
            atomicMax((int*)&g_dmax[1], __float_as_int(mm));
        }
    } else {
#pragma unroll
        for (int i = 0; i < 8; i++) {
            float gi = scat[base + i];
            float nv = vs[i] + s * floorf(gi * is);
            g_wh[(size_t)i * DCOLS + j] = __float2half_rn(nv);
        }
    }
}

// ---------------- HMMA GEMM (fp16, full-K, 3-stage cp.async) ----------------
#define GEMM_SMEM (3 * 32768)
#define BSWZ(k, cbyte) ((uint32_t)((k) * 256 + (cbyte)) ^ ((uint32_t)((k) & 7) << 4))
#define KTILES 32

__global__ void __launch_bounds__(256, 2) k_gemm(float* __restrict__ out) {
    extern __shared__ char smemraw[];
    uint32_t smb = smem_u32(smemraw);
    int tid = threadIdx.x, wid = tid >> 5, lane = tid & 31;
    int e = blockIdx.z, bm = blockIdx.y * 128, bn = blockIdx.x * 128;

    const __half* A = g_xh + (size_t)e * 2048  + (size_t)bm * 16384;
    const __half* B = g_wh + (size_t)e * DCOLS + bn;

    uint32_t aswz[4], bswz[4];
    size_t aofs[4], bofs[4];
#pragma unroll
    for (int i = 0; i < 4; i++) {
        int v = tid + i * 256;
        int arow = v >> 3, ac = v & 7;
        aswz[i] = SWZ128((uint32_t)(arow * 128 + ac * 16));
        aofs[i] = (size_t)arow * 16384 + ac * 8;
        int brow = v >> 4, bc = v & 15;
        bswz[i] = BSWZ(brow, bc * 16);
        bofs[i] = (size_t)brow * 1024 + bc * 8;
    }

    int wm = (wid & 1) * 64, wn = (wid >> 1) * 32;
    int a_row = lane & 15;
    int a_kb  = (lane >> 4) * 16;
    int b_krb = (lane & 7) + ((lane >> 3) & 1) * 8;
    int b_nch = (lane >> 4) * 8;

    float c[4][4][4];
#pragma unroll
    for (int mi = 0; mi < 4; mi++)
#pragma unroll
        for (int ni = 0; ni < 4; ni++)
#pragma unroll
            for (int q = 0; q < 4; q++) c[mi][ni][q] = 0.0f;

#pragma unroll
    for (int t = 0; t < 2; t++) {
        uint32_t base = smb + t * 32768;
        int k0 = t * 64;
#pragma unroll
        for (int i = 0; i < 4; i++) {
            CP_ASYNC16(base + aswz[i],         A + aofs[i] + k0);
            CP_ASYNC16(base + 16384 + bswz[i], B + bofs[i] + (size_t)k0 * 1024);
        }
        CP_COMMIT();
    }

#pragma unroll 1
    for (int t = 0; t < KTILES; t++) {
        if (t == KTILES - 1) { CP_WAIT(0); } else { CP_WAIT(1); }
        __syncthreads();
        if (t + 2 < KTILES) {
            uint32_t base = smb + ((t + 2) % 3) * 32768;
            int k0 = (t + 2) * 64;
#pragma unroll
            for (int i = 0; i < 4; i++) {
                CP_ASYNC16(base + aswz[i],         A + aofs[i] + k0);
                CP_ASYNC16(base + 16384 + bswz[i], B + bofs[i] + (size_t)k0 * 1024);
            }
            CP_COMMIT();
        }

        uint32_t base = smb + (t % 3) * 32768;
#pragma unroll
        for (int ks = 0; ks < 4; ks++) {
            uint32_t a[4][4], b[4][2];
#pragma unroll
            for (int mi = 0; mi < 4; mi++) {
                int row = wm + mi * 16 + a_row;
                uint32_t off = SWZ128((uint32_t)(row * 128 + ks * 32 + a_kb));
                ldsm_x4(a[mi][0], a[mi][1], a[mi][2], a[mi][3], base + off);
            }
#pragma unroll
            for (int np = 0; np < 2; np++) {
                int k_row = ks * 16 + b_krb;
                int n_col = wn + np * 16 + b_nch;
                uint32_t off = BSWZ(k_row, (n_col >> 3) << 4);
                uint32_t r0, r1, r2, r3;
                ldsm_x4t(r0, r1, r2, r3, base + 16384 + off);
                b[np * 2][0] = r0; b[np * 2][1] = r1;
                b[np * 2 + 1][0] = r2; b[np * 2 + 1][1] = r3;
            }
#pragma unroll
            for (int mi = 0; mi < 4; mi++)
#pragma unroll
                for (int ni = 0; ni < 4; ni++)
                    mma16816(c[mi][ni], a[mi], b[ni]);
        }
    }

    int group = lane >> 2, tig = lane & 3;
#pragma unroll
    for (int mi = 0; mi < 4; mi++) {
        int m0 = bm + wm + mi * 16 + group;
#pragma unroll
        for (int ni = 0; ni < 4; ni++) {
            int n0 = bn + wn + ni * 8 + tig * 2;
            float2 v0 = make_float2(c[mi][ni][0], c[mi][ni][1]);
            float2 v1 = make_float2(c[mi][ni][2], c[mi][ni][3]);
            *(float2*)(out + (size_t)m0 * 8192 + (size_t)e * 1024 + n0)       = v0;
            *(float2*)(out + (size_t)(m0 + 8) * 8192 + (size_t)e * 1024 + n0) = v1;
        }
    }
}

// ---------------- launch ----------------------------------------------------
extern "C" void kernel_launch(void* const* d_in, const int* in_sizes, int n_in,
                              void* d_out, int out_size) {
    const float* x = nullptr; const float* U = nullptr; const float* tm = nullptr;
    for (int i = 0; i < n_in; i++) {
        if (in_sizes[i] == NROW * DCOLS)      U  = (const float*)d_in[i];
        else if (in_sizes[i] == XELEMS)       x  = (const float*)d_in[i];
        else if (in_sizes[i] == DD2)          tm = (const float*)d_in[i];
    }
    float* out = (float*)d_out;

    cudaFuncSetAttribute(k_gemm, cudaFuncAttributeMaxDynamicSharedMemorySize, GEMM_SMEM);

    k_init<<<1, 256>>>();
    k_minmax_xhalf<<<2048, 256>>>(U, x);
    k_scales<<<4, 256>>>(tm);

    k_deltamax0<<<DCOLS / 512, 256>>>(U);      // 2-col (fast variant)
    k_hist<<<DCOLS / 1024, 256>>>(U, 0);       // 4-col (fast variant)
    k_finalize<<<1, 128>>>(U, 0);
    k_update<<<DCOLS / 256, 256>>>(U, 0);      // stores lattice codes, fused deltamax1

    k_hist<<<DCOLS / 1024, 256>>>(U, 1);       // 4-col
    k_finalize<<<1, 128>>>(U, 1);
    k_update<<<DCOLS / 256, 256>>>(U, 1);      // writes W fp16 directly

    dim3 gg(DD2 / 128, NBATCH / 128, NROW);
    k_gemm<<<gg, 256, GEMM_SMEM>>>(out);
}